// round 14
// baseline (speedup 1.0000x reference)
#include <cuda_runtime.h>
#include <cuda_fp16.h>
#include <cstdint>

// Problem constants
#define B_    4
#define T_    2048
#define C_DIM 1024
#define H_    16
#define D_    64
#define M_ROWS (B_*T_)      // 8192
#define QKV_N  (3*C_DIM)    // 3072
#define NEG_BIG (-3.0e38f)

// Scratch (device globals, fp16 payloads)
// g_q: A-frag-major per (bh, qblock, kt):   ((bh*16+qb)*2+kt)*2048 u32
// g_k: B-frag-major per (bh, keyblock, kt): (bh*32+kb*2+kt)*2048 u32  (n=key,k=d)
// g_v: B-frag-major per (bh, key32, dtile): bh*65536 + (k32*8+ntile)*128 u32 (n=d,k=key)
__device__ float g_q[4194304];
__device__ float g_k[4194304];
__device__ float g_v[4194304];
__device__ float g_y[4194304];    // half, fragment-major A-layout
__device__ float g_xr[4194304];   // half, fragment-major A-layout
__device__ float g_war[1572864];  // half, fragment-major B-layout
__device__ float g_wpr[524288];   // half, fragment-major B-layout

// ---------------------------------------------------------------------------
// Helpers
// ---------------------------------------------------------------------------
__device__ __forceinline__ uint32_t cvta_smem(const void* p) {
    uint32_t a;
    asm("{ .reg .u64 t; cvta.to.shared.u64 t, %1; cvt.u32.u64 %0, t; }"
        : "=r"(a) : "l"(p));
    return a;
}
__device__ __forceinline__ void cp_async16(uint32_t dst, const void* src) {
    asm volatile("cp.async.cg.shared.global [%0], [%1], 16;" :: "r"(dst), "l"(src));
}
__device__ __forceinline__ void cp_commit() { asm volatile("cp.async.commit_group;"); }
__device__ __forceinline__ void cp_wait0()  { asm volatile("cp.async.wait_group 0;"); }
__device__ __forceinline__ void cp_wait1()  { asm volatile("cp.async.wait_group 1;"); }

__device__ __forceinline__ uint32_t pack_h2(float a, float b) {
    __half2 h = __floats2half2_rn(a, b);
    return *reinterpret_cast<uint32_t*>(&h);
}
__device__ __forceinline__ void mma_f16(float* d, const uint32_t* a, const uint32_t* b) {
    asm volatile(
        "mma.sync.aligned.m16n8k16.row.col.f32.f16.f16.f32 "
        "{%0,%1,%2,%3}, {%4,%5,%6,%7}, {%8,%9}, {%0,%1,%2,%3};"
        : "+f"(d[0]), "+f"(d[1]), "+f"(d[2]), "+f"(d[3])
        : "r"(a[0]), "r"(a[1]), "r"(a[2]), "r"(a[3]), "r"(b[0]), "r"(b[1]));
}

// ---------------------------------------------------------------------------
// Prepass: fp32 -> fp16 fragment-major (unchanged)
// ---------------------------------------------------------------------------
__global__ void __launch_bounds__(256) permA_kernel(
    const float* __restrict__ in, uint32_t* __restrict__ out, int K)
{
    __shared__ float t[128][33];
    const int kt = blockIdx.x, mb = blockIdx.y;
    const int tid = threadIdx.x;
    const int nkt = K >> 5;
    const float* src = in + (size_t)mb * 128 * K + kt * 32;
    #pragma unroll
    for (int i = 0; i < 4; ++i) {
        const int row = (tid >> 3) + i * 32;
        const int c4  = (tid & 7) * 4;
        float4 v = *(const float4*)(src + (size_t)row * K + c4);
        t[row][c4] = v.x; t[row][c4+1] = v.y; t[row][c4+2] = v.z; t[row][c4+3] = v.w;
    }
    __syncthreads();
    uint32_t* dst = out + (size_t)(mb * nkt + kt) * 2048;
    #pragma unroll
    for (int i = 0; i < 8; ++i) {
        const int idx = tid + i * 256;
        const int tile = idx >> 7, lr = idx & 127;
        const int lane = lr >> 2, reg = lr & 3;
        const int mtile = tile >> 1, kstep = tile & 1;
        const int qr = lane >> 2, qc = lane & 3;
        const int m = mtile * 16 + qr + (reg & 1) * 8;
        const int kk = kstep * 16 + qc * 2 + (reg >> 1) * 8;
        dst[idx] = pack_h2(t[m][kk], t[m][kk + 1]);
    }
}

__global__ void __launch_bounds__(256) permB_kernel(
    const float* __restrict__ in, uint32_t* __restrict__ out, int K)
{
    __shared__ float t[128][33];
    const int kt = blockIdx.x, nb = blockIdx.y;
    const int tid = threadIdx.x;
    const int nkt = K >> 5;
    const float* src = in + (size_t)nb * 128 * K + kt * 32;
    #pragma unroll
    for (int i = 0; i < 4; ++i) {
        const int row = (tid >> 3) + i * 32;
        const int c4  = (tid & 7) * 4;
        float4 v = *(const float4*)(src + (size_t)row * K + c4);
        t[row][c4] = v.x; t[row][c4+1] = v.y; t[row][c4+2] = v.z; t[row][c4+3] = v.w;
    }
    __syncthreads();
    uint32_t* dst = out + (size_t)(nb * nkt + kt) * 2048;
    #pragma unroll
    for (int i = 0; i < 8; ++i) {
        const int idx = tid + i * 256;
        const int tile = idx >> 7, lr = idx & 127;
        const int lane = lr >> 2, reg = lr & 3;
        const int qr = lane >> 2, qc = lane & 3;
        const int n = tile * 8 + qr;
        const int kk = (reg >> 1) * 16 + qc * 2 + (reg & 1) * 8;
        dst[idx] = pack_h2(t[n][kk], t[n][kk + 1]);
    }
}

// ---------------------------------------------------------------------------
// fp16 mma GEMM: 128x128 tile, 64-k stages (A 16KB + B 16KB), 3 stages,
// single barrier per 64-k iteration (16 iters for K=1024). 8 warps 2x4.
// MODE 0: fp32 store. MODE 1: frag-major Q/K/V scatter.
// ---------------------------------------------------------------------------
#define NSTAGE 3
#define STG_U32 8192
#define GEMM_SMEM (NSTAGE * STG_U32 * 4)   // 98304

__device__ __forceinline__ void g_issue64(
    const uint32_t* __restrict__ Ab, const uint32_t* __restrict__ Wb,
    int kt2, uint32_t smem_base, int s, int tid)
{
    const uint32_t dst = smem_base + (s * STG_U32 + tid * 16) * 4;
    const uint32_t* a = Ab + (size_t)kt2 * 4096 + tid * 16;
    const uint32_t* b = Wb + (size_t)kt2 * 4096 + tid * 16;
    #pragma unroll
    for (int j = 0; j < 4; ++j) {
        cp_async16(dst + j * 16,            a + j * 4);
        cp_async16(dst + 4096 * 4 + j * 16, b + j * 4);
    }
    cp_commit();
}

template<int MODE>
__global__ void __launch_bounds__(256) gemm_f16_kernel(
    const uint32_t* __restrict__ A, const uint32_t* __restrict__ W,
    const float* __restrict__ bias, float* __restrict__ out,
    int N, int K)
{
    extern __shared__ float smf[];
    uint32_t* sm = (uint32_t*)smf;
    const int tid  = threadIdx.x;
    const int lane = tid & 31;
    const int wid  = tid >> 5;
    const int wm   = wid & 1;
    const int wn   = wid >> 1;
    const int qr   = lane >> 2;
    const int qc   = lane & 3;

    const int nkt = K >> 5;
    const int nk2 = K >> 6;
    const int mb = blockIdx.y, nb = blockIdx.x;
    const uint32_t* Ab = A + (size_t)mb * nkt * 2048;
    const uint32_t* Wb = W + (size_t)nb * nkt * 2048;
    const uint32_t smem_base = cvta_smem(sm);

    float acc[4][4][4];
    #pragma unroll
    for (int i = 0; i < 4; ++i)
        #pragma unroll
        for (int j = 0; j < 4; ++j)
            #pragma unroll
            for (int r = 0; r < 4; ++r) acc[i][j][r] = 0.f;

    g_issue64(Ab, Wb, 0, smem_base, 0, tid);
    g_issue64(Ab, Wb, 1, smem_base, 1, tid);

    for (int kt2 = 0; kt2 < nk2; ++kt2) {
        if (kt2 + 1 < nk2) cp_wait1(); else cp_wait0();
        __syncthreads();
        if (kt2 + 2 < nk2)
            g_issue64(Ab, Wb, kt2 + 2, smem_base, (kt2 + 2) % NSTAGE, tid);

        const uint32_t* stg = sm + (kt2 % NSTAGE) * STG_U32;
        #pragma unroll
        for (int half = 0; half < 2; ++half) {
            const uint32_t* Af = stg + half * 2048;
            const uint32_t* Bf = stg + 4096 + half * 2048;

            uint32_t bq[4][4];
            #pragma unroll
            for (int nt = 0; nt < 4; ++nt)
                *(uint4*)bq[nt] = *(const uint4*)(Bf + (wn * 4 + nt) * 128 + lane * 4);

            #pragma unroll
            for (int ks = 0; ks < 2; ++ks) {
                uint32_t af[4][4];
                #pragma unroll
                for (int mt = 0; mt < 4; ++mt)
                    *(uint4*)af[mt] = *(const uint4*)(Af + ((wm * 4 + mt) * 2 + ks) * 128 + lane * 4);
                #pragma unroll
                for (int mt = 0; mt < 4; ++mt)
                    #pragma unroll
                    for (int nt = 0; nt < 4; ++nt) {
                        uint32_t b2[2] = { bq[nt][ks * 2], bq[nt][ks * 2 + 1] };
                        mma_f16(acc[mt][nt], af[mt], b2);
                    }
            }
        }
    }

    const int rowBase = mb * 128, colBase = nb * 128;
    uint32_t* Qu = (uint32_t*)g_q;
    uint32_t* Ku = (uint32_t*)g_k;
    __half*   Vh = (__half*)g_v;
    #pragma unroll
    for (int nt = 0; nt < 4; ++nt) {
        const int n0 = colBase + wn * 32 + nt * 8 + qc * 2;
        const float b0 = bias[n0], b1 = bias[n0 + 1];
        #pragma unroll
        for (int mt = 0; mt < 4; ++mt) {
            const int m0 = rowBase + wm * 64 + mt * 16 + qr;
            float2 v0 = make_float2(acc[mt][nt][0] + b0, acc[mt][nt][1] + b1);
            float2 v1 = make_float2(acc[mt][nt][2] + b0, acc[mt][nt][3] + b1);
            if (MODE == 0) {
                *(float2*)(out + (size_t)m0 * N + n0)       = v0;
                *(float2*)(out + (size_t)(m0 + 8) * N + n0) = v1;
            } else {
                const int sector = n0 >> 10;          // 0=Q 1=K 2=V
                const int c  = n0 & 1023;
                const int hh = c >> 6, dd = c & 63;
                const int tt = m0 & 2047;
                const int bh = (m0 >> 11) * 16 + hh;
                const int d5 = dd & 31;
                if (sector == 0) {
                    const size_t base = ((size_t)(bh * 16 + (tt >> 7)) * 2 + (dd >> 5)) * 2048;
                    const int tile = ((tt >> 4) & 7) * 2 + ((d5 >> 4) & 1);
                    const int ln   = (tt & 7) * 4 + ((d5 >> 1) & 3);
                    const int reg0 = ((d5 >> 3) & 1) * 2;
                    uint2 u;
                    u.x = pack_h2(v0.x * 0.125f, v0.y * 0.125f);
                    u.y = pack_h2(v1.x * 0.125f, v1.y * 0.125f);
                    *(uint2*)(Qu + base + tile * 128 + ln * 4 + reg0) = u;
                } else if (sector == 1) {
                    const size_t base = ((size_t)bh * 32 + (tt >> 7) * 2 + (dd >> 5)) * 2048;
                    const int tile = (tt >> 3) & 15;
                    const int ln   = (tt & 7) * 4 + ((d5 >> 1) & 3);
                    const int reg  = ((d5 >> 4) & 1) * 2 + ((d5 >> 3) & 1);
                    Ku[base + tile * 128 + ln * 4 + reg]       = pack_h2(v0.x, v0.y);
                    Ku[base + (tile + 1) * 128 + ln * 4 + reg] = pack_h2(v1.x, v1.y);
                } else {
                    __half* vb = Vh + (size_t)bh * 131072;
                    #pragma unroll
                    for (int e = 0; e < 4; ++e) {
                        const int key = tt + (e >> 1) * 8;
                        const int d   = dd + (e & 1);
                        const float val = (e == 0) ? v0.x : (e == 1) ? v0.y
                                        : (e == 2) ? v1.x : v1.y;
                        const int kk = key & 31;
                        const size_t o = ((size_t)(key >> 5) * 8 + (d >> 3)) * 128
                                       + ((d & 7) * 4 + ((kk >> 1) & 3)) * 4
                                       + ((kk >> 4) & 1) * 2 + ((kk >> 3) & 1);
                        vb[o * 2 + (key & 1)] = __float2half_rn(val);
                    }
                }
            }
        }
    }
}

// ---------------------------------------------------------------------------
// fp16 flash attention: 128-key PAIRS per barrier (two 64-key sub-tiles
// computed back-to-back from one cp.async group). Q frags via LDG, K/V
// B-frags from smem, P in registers. 2 stages x 32 KB, 2 CTAs/SM.
// ---------------------------------------------------------------------------
#define PAIR_U32 8192                      // [K 4096][V 4096]
#define ATTN_SMEM (2 * PAIR_U32 * 4)       // 65536

__global__ void __launch_bounds__(256, 2) attn_f16_kernel(uint32_t* __restrict__ Yu)
{
    extern __shared__ float smf[];
    uint32_t* KV = (uint32_t*)smf;

    const int qt  = gridDim.x - 1 - blockIdx.x;
    const int bh  = blockIdx.y;
    const int b   = bh >> 4, h = bh & 15;
    const int tid = threadIdx.x;
    const int lane = tid & 31;
    const int w    = tid >> 5;
    const int qr   = lane >> 2;
    const int qc   = lane & 3;

    const uint32_t* Ku = (const uint32_t*)g_k + (size_t)bh * 65536;
    const uint32_t* Vu = (const uint32_t*)g_v + (size_t)bh * 65536;
    const uint32_t kv_b = cvta_smem(KV);

    // Prologue: issue KV pair 0 into stage 0 (K pair + V pair both contiguous)
    {
        const uint32_t* kc = Ku + tid * 16;
        const uint32_t* vc = Vu + tid * 16;
        #pragma unroll
        for (int j = 0; j < 4; ++j) {
            cp_async16(kv_b + (tid * 16 + j * 4) * 4,        kc + j * 4);
            cp_async16(kv_b + (4096 + tid * 16 + j * 4) * 4, vc + j * 4);
        }
        cp_commit();
    }

    // Q fragments: 4 direct LDG.128 (A-frag-major, pre-scaled)
    uint32_t qf[4][4];
    {
        const uint32_t* qb = (const uint32_t*)g_q + ((size_t)(bh * 16 + qt)) * 2 * 2048;
        #pragma unroll
        for (int ks = 0; ks < 4; ++ks)
            *(uint4*)qf[ks] = *(const uint4*)(qb + (ks >> 1) * 2048
                                              + (w * 2 + (ks & 1)) * 128 + lane * 4);
    }

    float m0 = NEG_BIG, m1 = NEG_BIG, l0 = 0.f, l1 = 0.f;
    float oacc[8][4];
    #pragma unroll
    for (int nt = 0; nt < 8; ++nt)
        #pragma unroll
        for (int r = 0; r < 4; ++r) oacc[nt][r] = 0.f;

    const int row0 = w * 16 + qr;

    for (int jp = 0; jp <= qt; ++jp) {
        cp_wait0();
        __syncthreads();   // pair jp data visible; all warps done with jp-1

        if (jp + 1 <= qt) {
            const uint32_t stg = kv_b + ((jp + 1) & 1) * PAIR_U32 * 4;
            const uint32_t* kc = Ku + (size_t)(jp + 1) * 4096 + tid * 16;
            const uint32_t* vc = Vu + (size_t)(jp + 1) * 4096 + tid * 16;
            #pragma unroll
            for (int j = 0; j < 4; ++j) {
                cp_async16(stg + (tid * 16 + j * 4) * 4,        kc + j * 4);
                cp_async16(stg + (4096 + tid * 16 + j * 4) * 4, vc + j * 4);
            }
            cp_commit();
        }

        const uint32_t* stgK = KV + (jp & 1) * PAIR_U32;
        const uint32_t* stgV = stgK + 4096;

        #pragma unroll
        for (int half = 0; half < 2; ++half) {
            const uint32_t* Ksub = stgK + half * 1024;   // K halves at +0, +2048(u32 1024*2)
            const uint32_t* Vsub = stgV + half * 2048;

            int ntmax = 8;
            if (jp == qt) {
                if (half == 0) { ntmax = 2 * w + 2; if (ntmax > 8) ntmax = 8; }
                else           { ntmax = 2 * w - 6; if (ntmax < 0) ntmax = 0; }
            }
            if (ntmax <= 0) continue;

            // ---- S = Q K^T ----
            float sacc[8][4];
            #pragma unroll
            for (int nt = 0; nt < 8; ++nt)
                #pragma unroll
                for (int r = 0; r < 4; ++r) sacc[nt][r] = 0.f;

            #pragma unroll
            for (int nt = 0; nt < 8; ++nt) {
                if (nt < ntmax) {
                    uint4 k0 = *(const uint4*)(Ksub + nt * 128 + lane * 4);
                    uint4 k1 = *(const uint4*)(Ksub + 2048 + nt * 128 + lane * 4);
                    uint32_t b0[2] = { k0.x, k0.y };
                    uint32_t b1[2] = { k0.z, k0.w };
                    uint32_t b2[2] = { k1.x, k1.y };
                    uint32_t b3[2] = { k1.z, k1.w };
                    mma_f16(sacc[nt], qf[0], b0);
                    mma_f16(sacc[nt], qf[1], b1);
                    mma_f16(sacc[nt], qf[2], b2);
                    mma_f16(sacc[nt], qf[3], b3);
                }
            }

            // ---- Causal mask (diagonal pair only) ----
            if (jp == qt) {
                const int rel = half * 64;
                #pragma unroll
                for (int nt = 0; nt < 8; ++nt) {
                    if (nt < ntmax) {
                        const int col = rel + nt * 8 + qc * 2;
                        if (col     > row0)     sacc[nt][0] = NEG_BIG;
                        if (col + 1 > row0)     sacc[nt][1] = NEG_BIG;
                        if (col     > row0 + 8) sacc[nt][2] = NEG_BIG;
                        if (col + 1 > row0 + 8) sacc[nt][3] = NEG_BIG;
                    }
                }
            }

            // ---- Online softmax; P packed into registers ----
            float rmax0 = NEG_BIG, rmax1 = NEG_BIG;
            #pragma unroll
            for (int nt = 0; nt < 8; ++nt) {
                if (nt < ntmax) {
                    rmax0 = fmaxf(rmax0, fmaxf(sacc[nt][0], sacc[nt][1]));
                    rmax1 = fmaxf(rmax1, fmaxf(sacc[nt][2], sacc[nt][3]));
                }
            }
            rmax0 = fmaxf(rmax0, __shfl_xor_sync(0xffffffffu, rmax0, 1));
            rmax0 = fmaxf(rmax0, __shfl_xor_sync(0xffffffffu, rmax0, 2));
            rmax1 = fmaxf(rmax1, __shfl_xor_sync(0xffffffffu, rmax1, 1));
            rmax1 = fmaxf(rmax1, __shfl_xor_sync(0xffffffffu, rmax1, 2));

            const float mn0 = fmaxf(m0, rmax0);
            const float mn1 = fmaxf(m1, rmax1);
            const float al0 = __expf(m0 - mn0);
            const float al1 = __expf(m1 - mn1);

            uint32_t pf[4][4];
            float rs0 = 0.f, rs1 = 0.f;
            #pragma unroll
            for (int nt = 0; nt < 8; ++nt) {
                if (nt < ntmax) {
                    const float p00 = __expf(sacc[nt][0] - mn0);
                    const float p01 = __expf(sacc[nt][1] - mn0);
                    const float p10 = __expf(sacc[nt][2] - mn1);
                    const float p11 = __expf(sacc[nt][3] - mn1);
                    rs0 += p00 + p01;
                    rs1 += p10 + p11;
                    const int ks = nt >> 1;
                    const int rb = (nt & 1) * 2;
                    pf[ks][rb]     = pack_h2(p00, p01);
                    pf[ks][rb + 1] = pack_h2(p10, p11);
                }
            }
            rs0 += __shfl_xor_sync(0xffffffffu, rs0, 1);
            rs0 += __shfl_xor_sync(0xffffffffu, rs0, 2);
            rs1 += __shfl_xor_sync(0xffffffffu, rs1, 1);
            rs1 += __shfl_xor_sync(0xffffffffu, rs1, 2);

            l0 = l0 * al0 + rs0;
            l1 = l1 * al1 + rs1;
            m0 = mn0;
            m1 = mn1;

            #pragma unroll
            for (int nt = 0; nt < 8; ++nt) {
                oacc[nt][0] *= al0; oacc[nt][1] *= al0;
                oacc[nt][2] *= al1; oacc[nt][3] *= al1;
            }

            // ---- O += P V ----
            const int kmax = ntmax >> 1;
            #pragma unroll
            for (int nt = 0; nt < 8; ++nt) {
                uint4 v0 = *(const uint4*)(Vsub + nt * 128 + lane * 4);
                uint32_t b0[2] = { v0.x, v0.y };
                uint32_t b1[2] = { v0.z, v0.w };
                mma_f16(oacc[nt], pf[0], b0);
                if (1 < kmax) mma_f16(oacc[nt], pf[1], b1);
                if (2 < kmax) {
                    uint4 v1 = *(const uint4*)(Vsub + 1024 + nt * 128 + lane * 4);
                    uint32_t b2[2] = { v1.x, v1.y };
                    uint32_t b3[2] = { v1.z, v1.w };
                    mma_f16(oacc[nt], pf[2], b2);
                    if (3 < kmax) mma_f16(oacc[nt], pf[3], b3);
                }
            }
        }
    }

    // Epilogue: normalize, pack fp16, scatter into fragment-major y
    const float inv0 = 1.0f / l0;
    const float inv1 = 1.0f / l1;
    const int mb = b * 16 + qt;
    #pragma unroll
    for (int nt = 0; nt < 8; ++nt) {
        const int ktc = h * 2 + (nt >> 2);
        const int kstep = (nt >> 1) & 1;
        const int rb = (nt & 1) * 2;
        uint32_t* blk = Yu + ((size_t)(mb * 32 + ktc) * 16 + (w * 2 + kstep)) * 128 + lane * 4;
        blk[rb]     = pack_h2(oacc[nt][0] * inv0, oacc[nt][1] * inv0);
        blk[rb + 1] = pack_h2(oacc[nt][2] * inv1, oacc[nt][3] * inv1);
    }
}

// ---------------------------------------------------------------------------
extern "C" void kernel_launch(void* const* d_in, const int* in_sizes, int n_in,
                              void* d_out, int out_size)
{
    const float* x      = (const float*)d_in[0];
    const float* w_attn = (const float*)d_in[1];
    const float* b_attn = (const float*)d_in[2];
    const float* w_proj = (const float*)d_in[3];
    const float* b_proj = (const float*)d_in[4];
    float* out = (float*)d_out;

    void *yv, *xv, *wav, *wpv;
    cudaGetSymbolAddress(&yv,  g_y);
    cudaGetSymbolAddress(&xv,  g_xr);
    cudaGetSymbolAddress(&wav, g_war);
    cudaGetSymbolAddress(&wpv, g_wpr);
    uint32_t* yu  = (uint32_t*)yv;
    uint32_t* xr  = (uint32_t*)xv;
    uint32_t* war = (uint32_t*)wav;
    uint32_t* wpr = (uint32_t*)wpv;

    cudaFuncSetAttribute(gemm_f16_kernel<1>,
                         cudaFuncAttributeMaxDynamicSharedMemorySize, GEMM_SMEM);
    cudaFuncSetAttribute(gemm_f16_kernel<0>,
                         cudaFuncAttributeMaxDynamicSharedMemorySize, GEMM_SMEM);
    cudaFuncSetAttribute(attn_f16_kernel,
                         cudaFuncAttributeMaxDynamicSharedMemorySize, ATTN_SMEM);

    // 0) Prepass: permute + fp16-round
    permA_kernel<<<dim3(32, 64), 256>>>(x,      xr,  C_DIM);
    permB_kernel<<<dim3(32, 24), 256>>>(w_attn, war, C_DIM);
    permB_kernel<<<dim3(32,  8), 256>>>(w_proj, wpr, C_DIM);

    // 1) QKV projection; epilogue emits fragment-major Q(scaled)/K/V
    dim3 g1(QKV_N / 128, M_ROWS / 128);   // 24 x 64
    gemm_f16_kernel<1><<<g1, 256, GEMM_SMEM>>>(xr, war, b_attn, nullptr, QKV_N, C_DIM);

    // 2) Causal flash attention -> y fragment-major fp16
    dim3 g2(T_ / 128, B_ * H_);           // 16 x 64
    attn_f16_kernel<<<g2, 256, ATTN_SMEM>>>(yu);

    // 3) Output projection -> d_out fp32
    dim3 g3(C_DIM / 128, M_ROWS / 128);   // 8 x 64
    gemm_f16_kernel<0><<<g3, 256, GEMM_SMEM>>>(yu, wpr, b_proj, out, C_DIM, C_DIM);
}

// round 17
// speedup vs baseline: 1.0074x; 1.0074x over previous
#include <cuda_runtime.h>
#include <cuda_fp16.h>
#include <cstdint>

// Problem constants
#define B_    4
#define T_    2048
#define C_DIM 1024
#define H_    16
#define D_    64
#define M_ROWS (B_*T_)      // 8192
#define QKV_N  (3*C_DIM)    // 3072
#define NEG_BIG (-3.0e38f)

// Scratch (device globals, fp16 payloads)
// g_q: A-frag-major per (bh, qblock, kt):   ((bh*16+qb)*2+kt)*2048 u32
// g_k: B-frag-major per (bh, keyblock, kt): (bh*32+kb*2+kt)*2048 u32  (n=key,k=d)
// g_v: B-frag-major per (bh, key32, dtile): bh*65536 + (k32*8+ntile)*128 u32 (n=d,k=key)
__device__ float g_q[4194304];
__device__ float g_k[4194304];
__device__ float g_v[4194304];
__device__ float g_y[4194304];    // half, fragment-major A-layout
__device__ float g_xr[4194304];   // half, fragment-major A-layout
__device__ float g_war[1572864];  // half, fragment-major B-layout
__device__ float g_wpr[524288];   // half, fragment-major B-layout

// ---------------------------------------------------------------------------
// Helpers
// ---------------------------------------------------------------------------
__device__ __forceinline__ uint32_t cvta_smem(const void* p) {
    uint32_t a;
    asm("{ .reg .u64 t; cvta.to.shared.u64 t, %1; cvt.u32.u64 %0, t; }"
        : "=r"(a) : "l"(p));
    return a;
}
__device__ __forceinline__ void cp_async16(uint32_t dst, const void* src) {
    asm volatile("cp.async.cg.shared.global [%0], [%1], 16;" :: "r"(dst), "l"(src));
}
__device__ __forceinline__ void cp_commit() { asm volatile("cp.async.commit_group;"); }
__device__ __forceinline__ void cp_wait0()  { asm volatile("cp.async.wait_group 0;"); }
__device__ __forceinline__ void cp_wait1()  { asm volatile("cp.async.wait_group 1;"); }

__device__ __forceinline__ uint32_t pack_h2(float a, float b) {
    __half2 h = __floats2half2_rn(a, b);
    return *reinterpret_cast<uint32_t*>(&h);
}
__device__ __forceinline__ void mma_f16(float* d, const uint32_t* a, const uint32_t* b) {
    asm volatile(
        "mma.sync.aligned.m16n8k16.row.col.f32.f16.f16.f32 "
        "{%0,%1,%2,%3}, {%4,%5,%6,%7}, {%8,%9}, {%0,%1,%2,%3};"
        : "+f"(d[0]), "+f"(d[1]), "+f"(d[2]), "+f"(d[3])
        : "r"(a[0]), "r"(a[1]), "r"(a[2]), "r"(a[3]), "r"(b[0]), "r"(b[1]));
}

// ---------------------------------------------------------------------------
// Prepass: fp32 -> fp16 fragment-major
// ---------------------------------------------------------------------------
__global__ void __launch_bounds__(256) permA_kernel(
    const float* __restrict__ in, uint32_t* __restrict__ out, int K)
{
    __shared__ float t[128][33];
    const int kt = blockIdx.x, mb = blockIdx.y;
    const int tid = threadIdx.x;
    const int nkt = K >> 5;
    const float* src = in + (size_t)mb * 128 * K + kt * 32;
    #pragma unroll
    for (int i = 0; i < 4; ++i) {
        const int row = (tid >> 3) + i * 32;
        const int c4  = (tid & 7) * 4;
        float4 v = *(const float4*)(src + (size_t)row * K + c4);
        t[row][c4] = v.x; t[row][c4+1] = v.y; t[row][c4+2] = v.z; t[row][c4+3] = v.w;
    }
    __syncthreads();
    uint32_t* dst = out + (size_t)(mb * nkt + kt) * 2048;
    #pragma unroll
    for (int i = 0; i < 8; ++i) {
        const int idx = tid + i * 256;
        const int tile = idx >> 7, lr = idx & 127;
        const int lane = lr >> 2, reg = lr & 3;
        const int mtile = tile >> 1, kstep = tile & 1;
        const int qr = lane >> 2, qc = lane & 3;
        const int m = mtile * 16 + qr + (reg & 1) * 8;
        const int kk = kstep * 16 + qc * 2 + (reg >> 1) * 8;
        dst[idx] = pack_h2(t[m][kk], t[m][kk + 1]);
    }
}

__global__ void __launch_bounds__(256) permB_kernel(
    const float* __restrict__ in, uint32_t* __restrict__ out, int K)
{
    __shared__ float t[128][33];
    const int kt = blockIdx.x, nb = blockIdx.y;
    const int tid = threadIdx.x;
    const int nkt = K >> 5;
    const float* src = in + (size_t)nb * 128 * K + kt * 32;
    #pragma unroll
    for (int i = 0; i < 4; ++i) {
        const int row = (tid >> 3) + i * 32;
        const int c4  = (tid & 7) * 4;
        float4 v = *(const float4*)(src + (size_t)row * K + c4);
        t[row][c4] = v.x; t[row][c4+1] = v.y; t[row][c4+2] = v.z; t[row][c4+3] = v.w;
    }
    __syncthreads();
    uint32_t* dst = out + (size_t)(nb * nkt + kt) * 2048;
    #pragma unroll
    for (int i = 0; i < 8; ++i) {
        const int idx = tid + i * 256;
        const int tile = idx >> 7, lr = idx & 127;
        const int lane = lr >> 2, reg = lr & 3;
        const int qr = lane >> 2, qc = lane & 3;
        const int n = tile * 8 + qr;
        const int kk = (reg >> 1) * 16 + qc * 2 + (reg & 1) * 8;
        dst[idx] = pack_h2(t[n][kk], t[n][kk + 1]);
    }
}

// ---------------------------------------------------------------------------
// fp16 mma GEMM: 128x128 tile, 64-k stages (A 16KB + B 16KB), 3 stages,
// single barrier per 64-k iteration (16 iters for K=1024). 8 warps 2x4.
// MODE 0: fp32 store. MODE 1: frag-major Q/K/V scatter.
// ---------------------------------------------------------------------------
#define NSTAGE 3
#define STG_U32 8192
#define GEMM_SMEM (NSTAGE * STG_U32 * 4)   // 98304

__device__ __forceinline__ void g_issue64(
    const uint32_t* __restrict__ Ab, const uint32_t* __restrict__ Wb,
    int kt2, uint32_t smem_base, int s, int tid)
{
    const uint32_t dst = smem_base + (s * STG_U32 + tid * 16) * 4;
    const uint32_t* a = Ab + (size_t)kt2 * 4096 + tid * 16;
    const uint32_t* b = Wb + (size_t)kt2 * 4096 + tid * 16;
    #pragma unroll
    for (int j = 0; j < 4; ++j) {
        cp_async16(dst + j * 16,            a + j * 4);
        cp_async16(dst + 4096 * 4 + j * 16, b + j * 4);
    }
    cp_commit();
}

template<int MODE>
__global__ void __launch_bounds__(256) gemm_f16_kernel(
    const uint32_t* __restrict__ A, const uint32_t* __restrict__ W,
    const float* __restrict__ bias, float* __restrict__ out,
    int N, int K)
{
    extern __shared__ float smf[];
    uint32_t* sm = (uint32_t*)smf;
    const int tid  = threadIdx.x;
    const int lane = tid & 31;
    const int wid  = tid >> 5;
    const int wm   = wid & 1;
    const int wn   = wid >> 1;
    const int qr   = lane >> 2;
    const int qc   = lane & 3;

    const int nkt = K >> 5;
    const int nk2 = K >> 6;
    const int mb = blockIdx.y, nb = blockIdx.x;
    const uint32_t* Ab = A + (size_t)mb * nkt * 2048;
    const uint32_t* Wb = W + (size_t)nb * nkt * 2048;
    const uint32_t smem_base = cvta_smem(sm);

    float acc[4][4][4];
    #pragma unroll
    for (int i = 0; i < 4; ++i)
        #pragma unroll
        for (int j = 0; j < 4; ++j)
            #pragma unroll
            for (int r = 0; r < 4; ++r) acc[i][j][r] = 0.f;

    g_issue64(Ab, Wb, 0, smem_base, 0, tid);
    g_issue64(Ab, Wb, 1, smem_base, 1, tid);

    for (int kt2 = 0; kt2 < nk2; ++kt2) {
        if (kt2 + 1 < nk2) cp_wait1(); else cp_wait0();
        __syncthreads();   // all warps done with stage (kt2-1)%3 before reuse
        if (kt2 + 2 < nk2)
            g_issue64(Ab, Wb, kt2 + 2, smem_base, (kt2 + 2) % NSTAGE, tid);

        const uint32_t* stg = sm + (kt2 % NSTAGE) * STG_U32;
        #pragma unroll
        for (int half = 0; half < 2; ++half) {
            const uint32_t* Af = stg + half * 2048;
            const uint32_t* Bf = stg + 4096 + half * 2048;

            uint32_t bq[4][4];
            #pragma unroll
            for (int nt = 0; nt < 4; ++nt)
                *(uint4*)bq[nt] = *(const uint4*)(Bf + (wn * 4 + nt) * 128 + lane * 4);

            #pragma unroll
            for (int ks = 0; ks < 2; ++ks) {
                uint32_t af[4][4];
                #pragma unroll
                for (int mt = 0; mt < 4; ++mt)
                    *(uint4*)af[mt] = *(const uint4*)(Af + ((wm * 4 + mt) * 2 + ks) * 128 + lane * 4);
                #pragma unroll
                for (int mt = 0; mt < 4; ++mt)
                    #pragma unroll
                    for (int nt = 0; nt < 4; ++nt) {
                        uint32_t b2[2] = { bq[nt][ks * 2], bq[nt][ks * 2 + 1] };
                        mma_f16(acc[mt][nt], af[mt], b2);
                    }
            }
        }
    }

    const int rowBase = mb * 128, colBase = nb * 128;
    uint32_t* Qu = (uint32_t*)g_q;
    uint32_t* Ku = (uint32_t*)g_k;
    __half*   Vh = (__half*)g_v;
    #pragma unroll
    for (int nt = 0; nt < 4; ++nt) {
        const int n0 = colBase + wn * 32 + nt * 8 + qc * 2;
        const float b0 = bias[n0], b1 = bias[n0 + 1];
        #pragma unroll
        for (int mt = 0; mt < 4; ++mt) {
            const int m0 = rowBase + wm * 64 + mt * 16 + qr;
            float2 v0 = make_float2(acc[mt][nt][0] + b0, acc[mt][nt][1] + b1);
            float2 v1 = make_float2(acc[mt][nt][2] + b0, acc[mt][nt][3] + b1);
            if (MODE == 0) {
                *(float2*)(out + (size_t)m0 * N + n0)       = v0;
                *(float2*)(out + (size_t)(m0 + 8) * N + n0) = v1;
            } else {
                const int sector = n0 >> 10;          // 0=Q 1=K 2=V
                const int c  = n0 & 1023;
                const int hh = c >> 6, dd = c & 63;
                const int tt = m0 & 2047;
                const int bh = (m0 >> 11) * 16 + hh;
                const int d5 = dd & 31;
                if (sector == 0) {
                    const size_t base = ((size_t)(bh * 16 + (tt >> 7)) * 2 + (dd >> 5)) * 2048;
                    const int tile = ((tt >> 4) & 7) * 2 + ((d5 >> 4) & 1);
                    const int ln   = (tt & 7) * 4 + ((d5 >> 1) & 3);
                    const int reg0 = ((d5 >> 3) & 1) * 2;
                    uint2 u;
                    u.x = pack_h2(v0.x * 0.125f, v0.y * 0.125f);
                    u.y = pack_h2(v1.x * 0.125f, v1.y * 0.125f);
                    *(uint2*)(Qu + base + tile * 128 + ln * 4 + reg0) = u;
                } else if (sector == 1) {
                    const size_t base = ((size_t)bh * 32 + (tt >> 7) * 2 + (dd >> 5)) * 2048;
                    const int tile = (tt >> 3) & 15;
                    const int ln   = (tt & 7) * 4 + ((d5 >> 1) & 3);
                    const int reg  = ((d5 >> 4) & 1) * 2 + ((d5 >> 3) & 1);
                    Ku[base + tile * 128 + ln * 4 + reg]       = pack_h2(v0.x, v0.y);
                    Ku[base + (tile + 1) * 128 + ln * 4 + reg] = pack_h2(v1.x, v1.y);
                } else {
                    __half* vb = Vh + (size_t)bh * 131072;
                    #pragma unroll
                    for (int e = 0; e < 4; ++e) {
                        const int key = tt + (e >> 1) * 8;
                        const int d   = dd + (e & 1);
                        const float val = (e == 0) ? v0.x : (e == 1) ? v0.y
                                        : (e == 2) ? v1.x : v1.y;
                        const int kk = key & 31;
                        const size_t o = ((size_t)(key >> 5) * 8 + (d >> 3)) * 128
                                       + ((d & 7) * 4 + ((kk >> 1) & 3)) * 4
                                       + ((kk >> 4) & 1) * 2 + ((kk >> 3) & 1);
                        vb[o * 2 + (key & 1)] = __float2half_rn(val);
                    }
                }
            }
        }
    }
}

// ---------------------------------------------------------------------------
// fp16 flash attention (ROUND-11 VERSION, verbatim — known good at 469.5us):
// 64-key tiles, double-buffered K/V via cp.async (16 KB/stage), Q frags via
// LDG, K/V B-frags from smem, P in registers. 2 CTAs/SM.
// ---------------------------------------------------------------------------
#define KV_U32 4096
#define ATTN_SMEM (2 * KV_U32 * 4)   // 32768

__global__ void __launch_bounds__(256, 2) attn_f16_kernel(uint32_t* __restrict__ Yu)
{
    extern __shared__ float smf[];
    uint32_t* KV = (uint32_t*)smf;

    const int qt  = gridDim.x - 1 - blockIdx.x;
    const int bh  = blockIdx.y;
    const int b   = bh >> 4, h = bh & 15;
    const int tid = threadIdx.x;
    const int lane = tid & 31;
    const int w    = tid >> 5;
    const int qr   = lane >> 2;
    const int qc   = lane & 3;

    const uint32_t* Ku = (const uint32_t*)g_k + (size_t)bh * 65536;
    const uint32_t* Vu = (const uint32_t*)g_v + (size_t)bh * 65536;
    const uint32_t kv_b = cvta_smem(KV);

    // Prologue: issue KV tile 0 into stage 0
    {
        cp_async16(kv_b + tid * 16,              Ku + tid * 4);          // K kt0
        cp_async16(kv_b + 4096 + tid * 16,       Ku + 2048 + tid * 4);   // K kt1
        cp_async16(kv_b + 8192 + tid * 16,       Vu + tid * 4);          // V k32=0
        cp_async16(kv_b + 12288 + tid * 16,      Vu + 1024 + tid * 4);   // V k32=1
        cp_commit();
    }

    // Q fragments: 4 direct LDG.128 (A-frag-major, pre-scaled)
    uint32_t qf[4][4];
    {
        const uint32_t* qb = (const uint32_t*)g_q + ((size_t)(bh * 16 + qt)) * 2 * 2048;
        #pragma unroll
        for (int ks = 0; ks < 4; ++ks)
            *(uint4*)qf[ks] = *(const uint4*)(qb + (ks >> 1) * 2048
                                              + (w * 2 + (ks & 1)) * 128 + lane * 4);
    }

    float m0 = NEG_BIG, m1 = NEG_BIG, l0 = 0.f, l1 = 0.f;
    float oacc[8][4];
    #pragma unroll
    for (int nt = 0; nt < 8; ++nt)
        #pragma unroll
        for (int r = 0; r < 4; ++r) oacc[nt][r] = 0.f;

    const int row0 = w * 16 + qr;
    const int jmax = 2 * qt + 1;

    for (int j = 0; j <= jmax; ++j) {
        cp_wait0();
        __syncthreads();   // stage (j&1) data visible; all warps done with j-1

        if (j + 1 <= jmax) {
            const int jn = j + 1;
            const uint32_t stg = kv_b + (jn & 1) * KV_U32 * 4;
            const uint32_t* Kc = Ku + ((jn >> 1) * 2) * 2048 + (jn & 1) * 1024;
            const uint32_t* Vc = Vu + (size_t)(2 * jn) * 1024;
            cp_async16(stg + tid * 16,         Kc + tid * 4);
            cp_async16(stg + 4096 + tid * 16,  Kc + 2048 + tid * 4);
            cp_async16(stg + 8192 + tid * 16,  Vc + tid * 4);
            cp_async16(stg + 12288 + tid * 16, Vc + 1024 + tid * 4);
            cp_commit();
        }

        const uint32_t* Ksm = KV + (j & 1) * KV_U32;
        const uint32_t* Vsm = Ksm + 2048;

        int ntmax = 8;
        if (j == 2 * qt) {
            ntmax = 2 * w + 2; if (ntmax > 8) ntmax = 8;
        } else if (j == 2 * qt + 1) {
            ntmax = 2 * w - 6; if (ntmax < 0) ntmax = 0;
        }

        if (ntmax > 0) {
            // ---- S = Q K^T ----
            float sacc[8][4];
            #pragma unroll
            for (int nt = 0; nt < 8; ++nt)
                #pragma unroll
                for (int r = 0; r < 4; ++r) sacc[nt][r] = 0.f;

            #pragma unroll
            for (int nt = 0; nt < 8; ++nt) {
                if (nt < ntmax) {
                    uint4 k0 = *(const uint4*)(Ksm + nt * 128 + lane * 4);
                    uint4 k1 = *(const uint4*)(Ksm + 1024 + nt * 128 + lane * 4);
                    uint32_t b0[2] = { k0.x, k0.y };
                    uint32_t b1[2] = { k0.z, k0.w };
                    uint32_t b2[2] = { k1.x, k1.y };
                    uint32_t b3[2] = { k1.z, k1.w };
                    mma_f16(sacc[nt], qf[0], b0);
                    mma_f16(sacc[nt], qf[1], b1);
                    mma_f16(sacc[nt], qf[2], b2);
                    mma_f16(sacc[nt], qf[3], b3);
                }
            }

            // ---- Causal mask (diagonal tiles) ----
            if (j >= 2 * qt) {
                const int rel = (j - 2 * qt) * 64;
                #pragma unroll
                for (int nt = 0; nt < 8; ++nt) {
                    if (nt < ntmax) {
                        const int col = rel + nt * 8 + qc * 2;
                        if (col     > row0)     sacc[nt][0] = NEG_BIG;
                        if (col + 1 > row0)     sacc[nt][1] = NEG_BIG;
                        if (col     > row0 + 8) sacc[nt][2] = NEG_BIG;
                        if (col + 1 > row0 + 8) sacc[nt][3] = NEG_BIG;
                    }
                }
            }

            // ---- Online softmax; P packed straight into registers ----
            float rmax0 = NEG_BIG, rmax1 = NEG_BIG;
            #pragma unroll
            for (int nt = 0; nt < 8; ++nt) {
                if (nt < ntmax) {
                    rmax0 = fmaxf(rmax0, fmaxf(sacc[nt][0], sacc[nt][1]));
                    rmax1 = fmaxf(rmax1, fmaxf(sacc[nt][2], sacc[nt][3]));
                }
            }
            rmax0 = fmaxf(rmax0, __shfl_xor_sync(0xffffffffu, rmax0, 1));
            rmax0 = fmaxf(rmax0, __shfl_xor_sync(0xffffffffu, rmax0, 2));
            rmax1 = fmaxf(rmax1, __shfl_xor_sync(0xffffffffu, rmax1, 1));
            rmax1 = fmaxf(rmax1, __shfl_xor_sync(0xffffffffu, rmax1, 2));

            const float mn0 = fmaxf(m0, rmax0);
            const float mn1 = fmaxf(m1, rmax1);
            const float al0 = __expf(m0 - mn0);
            const float al1 = __expf(m1 - mn1);

            uint32_t pf[4][4];
            float rs0 = 0.f, rs1 = 0.f;
            #pragma unroll
            for (int nt = 0; nt < 8; ++nt) {
                if (nt < ntmax) {
                    const float p00 = __expf(sacc[nt][0] - mn0);
                    const float p01 = __expf(sacc[nt][1] - mn0);
                    const float p10 = __expf(sacc[nt][2] - mn1);
                    const float p11 = __expf(sacc[nt][3] - mn1);
                    rs0 += p00 + p01;
                    rs1 += p10 + p11;
                    const int ks = nt >> 1;
                    const int rb = (nt & 1) * 2;
                    pf[ks][rb]     = pack_h2(p00, p01);
                    pf[ks][rb + 1] = pack_h2(p10, p11);
                }
            }
            rs0 += __shfl_xor_sync(0xffffffffu, rs0, 1);
            rs0 += __shfl_xor_sync(0xffffffffu, rs0, 2);
            rs1 += __shfl_xor_sync(0xffffffffu, rs1, 1);
            rs1 += __shfl_xor_sync(0xffffffffu, rs1, 2);

            l0 = l0 * al0 + rs0;
            l1 = l1 * al1 + rs1;
            m0 = mn0;
            m1 = mn1;

            #pragma unroll
            for (int nt = 0; nt < 8; ++nt) {
                oacc[nt][0] *= al0; oacc[nt][1] *= al0;
                oacc[nt][2] *= al1; oacc[nt][3] *= al1;
            }

            // ---- O += P V (P in registers; V B-frags from smem) ----
            const int kmax = ntmax >> 1;
            #pragma unroll
            for (int nt = 0; nt < 8; ++nt) {
                uint4 v0 = *(const uint4*)(Vsm + nt * 128 + lane * 4);
                uint32_t b0[2] = { v0.x, v0.y };
                uint32_t b1[2] = { v0.z, v0.w };
                mma_f16(oacc[nt], pf[0], b0);
                if (1 < kmax) mma_f16(oacc[nt], pf[1], b1);
                if (2 < kmax) {
                    uint4 v1 = *(const uint4*)(Vsm + 1024 + nt * 128 + lane * 4);
                    uint32_t b2[2] = { v1.x, v1.y };
                    uint32_t b3[2] = { v1.z, v1.w };
                    mma_f16(oacc[nt], pf[2], b2);
                    if (3 < kmax) mma_f16(oacc[nt], pf[3], b3);
                }
            }
        }
    }

    // Epilogue: normalize, pack fp16, scatter into fragment-major y
    const float inv0 = 1.0f / l0;
    const float inv1 = 1.0f / l1;
    const int mb = b * 16 + qt;
    #pragma unroll
    for (int nt = 0; nt < 8; ++nt) {
        const int ktc = h * 2 + (nt >> 2);
        const int kstep = (nt >> 1) & 1;
        const int rb = (nt & 1) * 2;
        uint32_t* blk = Yu + ((size_t)(mb * 32 + ktc) * 16 + (w * 2 + kstep)) * 128 + lane * 4;
        blk[rb]     = pack_h2(oacc[nt][0] * inv0, oacc[nt][1] * inv0);
        blk[rb + 1] = pack_h2(oacc[nt][2] * inv1, oacc[nt][3] * inv1);
    }
}

// ---------------------------------------------------------------------------
extern "C" void kernel_launch(void* const* d_in, const int* in_sizes, int n_in,
                              void* d_out, int out_size)
{
    const float* x      = (const float*)d_in[0];
    const float* w_attn = (const float*)d_in[1];
    const float* b_attn = (const float*)d_in[2];
    const float* w_proj = (const float*)d_in[3];
    const float* b_proj = (const float*)d_in[4];
    float* out = (float*)d_out;

    void *yv, *xv, *wav, *wpv;
    cudaGetSymbolAddress(&yv,  g_y);
    cudaGetSymbolAddress(&xv,  g_xr);
    cudaGetSymbolAddress(&wav, g_war);
    cudaGetSymbolAddress(&wpv, g_wpr);
    uint32_t* yu  = (uint32_t*)yv;
    uint32_t* xr  = (uint32_t*)xv;
    uint32_t* war = (uint32_t*)wav;
    uint32_t* wpr = (uint32_t*)wpv;

    cudaFuncSetAttribute(gemm_f16_kernel<1>,
                         cudaFuncAttributeMaxDynamicSharedMemorySize, GEMM_SMEM);
    cudaFuncSetAttribute(gemm_f16_kernel<0>,
                         cudaFuncAttributeMaxDynamicSharedMemorySize, GEMM_SMEM);
    cudaFuncSetAttribute(attn_f16_kernel,
                         cudaFuncAttributeMaxDynamicSharedMemorySize, ATTN_SMEM);

    // 0) Prepass: permute + fp16-round
    permA_kernel<<<dim3(32, 64), 256>>>(x,      xr,  C_DIM);
    permB_kernel<<<dim3(32, 24), 256>>>(w_attn, war, C_DIM);
    permB_kernel<<<dim3(32,  8), 256>>>(w_proj, wpr, C_DIM);

    // 1) QKV projection; epilogue emits fragment-major Q(scaled)/K/V
    dim3 g1(QKV_N / 128, M_ROWS / 128);   // 24 x 64
    gemm_f16_kernel<1><<<g1, 256, GEMM_SMEM>>>(xr, war, b_attn, nullptr, QKV_N, C_DIM);

    // 2) Causal flash attention -> y fragment-major fp16
    dim3 g2(T_ / 128, B_ * H_);           // 16 x 64
    attn_f16_kernel<<<g2, 256, ATTN_SMEM>>>(yu);

    // 3) Output projection -> d_out fp32
    dim3 g3(C_DIM / 128, M_ROWS / 128);   // 8 x 64
    gemm_f16_kernel<0><<<g3, 256, GEMM_SMEM>>>(yu, wpr, b_proj, out, C_DIM, C_DIM);
}